// round 1
// baseline (speedup 1.0000x reference)
#include <cuda_runtime.h>
#include <math.h>

#define NA   8192
#define NE   262144
#define NMOL 128
#define FF   128
#define RR   20
#define LL   3
#define PI_F 3.14159265358979f

// ---------------- scratch (device globals; no runtime alloc allowed) -------
__device__ float g_s  [NA * FF];
__device__ float g_vA [NA * 3 * FF];
__device__ float g_vB [NA * 3 * FF];
__device__ float g_h  [NA * FF];
__device__ float g_phi[NA * 3 * FF];
__device__ float g_uv [NA * 3 * FF];
__device__ float g_vv [NA * 3 * FF];
__device__ float g_cat[NA * 2 * FF];
__device__ float g_ah [NA * FF];
__device__ float g_a  [NA * 3 * FF];
__device__ float g_egeo[NE * 24];   // per sorted edge: rbf*fc[20], fc, unit[3]
__device__ int   g_esrc[NE];
__device__ int   g_rowstart[NA + 1];
__device__ int   g_cursor[NA];
__device__ int   g_count[NA];

// ---------------- tiny utility kernels -------------------------------------
__global__ void zero_f_kernel(float* p, int n) {
    int i = blockIdx.x * blockDim.x + threadIdx.x;
    for (; i < n; i += gridDim.x * blockDim.x) p[i] = 0.f;
}
__global__ void zero_i_kernel(int* p, int n) {
    int i = blockIdx.x * blockDim.x + threadIdx.x;
    for (; i < n; i += gridDim.x * blockDim.x) p[i] = 0;
}

__global__ void embed_kernel(const int* __restrict__ z,
                             const float* __restrict__ embed,
                             float* __restrict__ s) {
    int i = blockIdx.x * blockDim.x + threadIdx.x;
    if (i >= NA * FF) return;
    int atom = i >> 7, f = i & 127;
    s[i] = embed[z[atom] * FF + f];
}

// ---------------- CSR build + edge geometry --------------------------------
__global__ void count_kernel(const int* __restrict__ dst, int* __restrict__ cnt) {
    int e = blockIdx.x * blockDim.x + threadIdx.x;
    if (e < NE) atomicAdd(&cnt[dst[e]], 1);
}

__global__ void scan_kernel(const int* __restrict__ cnt,
                            int* __restrict__ rowstart,
                            int* __restrict__ cursor) {
    __shared__ int part[1024];
    int t = threadIdx.x;                 // 1024 threads, 8 items each
    int loc[8], ex[8];
    int run = 0;
#pragma unroll
    for (int i = 0; i < 8; i++) {
        loc[i] = cnt[t * 8 + i];
        ex[i]  = run;
        run   += loc[i];
    }
    part[t] = run;
    __syncthreads();
    for (int off = 1; off < 1024; off <<= 1) {
        int v = (t >= off) ? part[t - off] : 0;
        __syncthreads();
        part[t] += v;
        __syncthreads();
    }
    int base = (t > 0) ? part[t - 1] : 0;
#pragma unroll
    for (int i = 0; i < 8; i++) {
        int rs = base + ex[i];
        rowstart[t * 8 + i] = rs;
        cursor[t * 8 + i]   = rs;
    }
    if (t == 1023) rowstart[NA] = part[1023];
}

__global__ void fill_kernel(const int* __restrict__ src,
                            const int* __restrict__ dst,
                            const float* __restrict__ pos,
                            int* __restrict__ cursor,
                            float* __restrict__ egeo,
                            int* __restrict__ esrc) {
    int e = blockIdx.x * blockDim.x + threadIdx.x;
    if (e >= NE) return;
    int sd = src[e], dd = dst[e];
    int p = atomicAdd(&cursor[dd], 1);
    float dx = pos[dd * 3 + 0] - pos[sd * 3 + 0];
    float dy = pos[dd * 3 + 1] - pos[sd * 3 + 1];
    float dz = pos[dd * 3 + 2] - pos[sd * 3 + 2];
    float d  = sqrtf(dx * dx + dy * dy + dz * dz + 1e-8f);
    float inv = 1.f / d;
    float fc = 0.5f * (cosf(PI_F * d / 5.0f) + 1.0f) * (d < 5.0f ? 1.f : 0.f);
    float* g = egeo + (long long)p * 24;
#pragma unroll
    for (int r = 0; r < RR; r++) {
        float freq = (float)(r + 1) * (PI_F / 5.0f);
        g[r] = sinf(d * freq) * inv * fc;   // rbf * fc  (fc folded in)
    }
    g[20] = fc;
    g[21] = dx * inv; g[22] = dy * inv; g[23] = dz * inv;
    esrc[p] = sd;
}

// ---------------- generic fp32 GEMM: C = act(A[M,K] @ W[K,N] + bias) -------
// BM=128, BN=64, BK=16, 256 threads, 8x4 per thread.
template <bool SILU>
__global__ __launch_bounds__(256, 4)
void gemm_kernel(const float* __restrict__ A, const float* __restrict__ W,
                 const float* __restrict__ bias, float* __restrict__ C,
                 int M, int N, int K) {
    __shared__ __align__(16) float As[16][128];
    __shared__ __align__(16) float Ws[16][64];
    int bn = blockIdx.x * 64;
    int bm = blockIdx.y * 128;
    int tid = threadIdx.x;
    int tx = tid & 15, ty = tid >> 4;
    float acc[8][4] = {};

    for (int k0 = 0; k0 < K; k0 += 16) {
#pragma unroll
        for (int p = 0; p < 2; p++) {
            int idx = tid + p * 256;        // 0..511
            int row = idx >> 2;             // 0..127
            int kc  = (idx & 3) * 4;        // 0,4,8,12
            float4 va = *(const float4*)&A[(long long)(bm + row) * K + k0 + kc];
            As[kc + 0][row] = va.x;
            As[kc + 1][row] = va.y;
            As[kc + 2][row] = va.z;
            As[kc + 3][row] = va.w;
        }
        {
            int kr = tid >> 4;              // 0..15
            int nc = (tid & 15) * 4;        // 0..60
            float4 vw = *(const float4*)&W[(long long)(k0 + kr) * N + bn + nc];
            *(float4*)&Ws[kr][nc] = vw;
        }
        __syncthreads();
#pragma unroll
        for (int k = 0; k < 16; k++) {
            float a[8], b[4];
            *(float4*)&a[0] = *(const float4*)&As[k][ty * 8];
            *(float4*)&a[4] = *(const float4*)&As[k][ty * 8 + 4];
            *(float4*)&b[0] = *(const float4*)&Ws[k][tx * 4];
#pragma unroll
            for (int i = 0; i < 8; i++)
#pragma unroll
                for (int j = 0; j < 4; j++)
                    acc[i][j] = fmaf(a[i], b[j], acc[i][j]);
        }
        __syncthreads();
    }
#pragma unroll
    for (int i = 0; i < 8; i++) {
        long long row = bm + ty * 8 + i;
#pragma unroll
        for (int j = 0; j < 4; j++) {
            int col = bn + tx * 4 + j;
            float x = acc[i][j];
            if (bias) x += bias[col];
            if (SILU) x = x / (1.f + __expf(-x));
            C[row * N + col] = x;
        }
    }
}

// ---------------- message pass (CSR gather, no atomics) ---------------------
#define APB 4    // atoms per block
#define CH  16   // edges staged per chunk
__global__ __launch_bounds__(128, 4)
void msg_kernel(const float* __restrict__ phi, const float* __restrict__ vin,
                float* __restrict__ s, float* __restrict__ vout,
                const float* __restrict__ rbfW, const float* __restrict__ rbfB,
                const float* __restrict__ egeo, const int* __restrict__ esrc,
                const int* __restrict__ rowstart) {
    int f = threadIdx.x;                  // feature 0..127
    float w1[RR], w2[RR], w3[RR];
#pragma unroll
    for (int r = 0; r < RR; r++) {
        w1[r] = rbfW[r * 384 + f];
        w2[r] = rbfW[r * 384 + 128 + f];
        w3[r] = rbfW[r * 384 + 256 + f];
    }
    float b1 = rbfB[f], b2 = rbfB[128 + f], b3 = rbfB[256 + f];

    __shared__ float sG[CH * 24];
    __shared__ int   sS[CH];

    int a0 = blockIdx.x * APB;
    for (int a = a0; a < a0 + APB; a++) {
        int beg = rowstart[a], end = rowstart[a + 1];
        float ds = 0.f, dv0 = 0.f, dv1 = 0.f, dv2 = 0.f;
        for (int c0 = beg; c0 < end; c0 += CH) {
            int nc = min(CH, end - c0);
            __syncthreads();
            for (int t = f; t < nc * 24; t += 128)
                sG[t] = egeo[(long long)c0 * 24 + t];
            if (f < nc) sS[f] = esrc[c0 + f];
            __syncthreads();
            for (int k = 0; k < nc; k++) {
                const float* gk = &sG[k * 24];
                float fc = gk[20];
                float u0 = gk[21], u1 = gk[22], u2 = gk[23];
                int src = sS[k];
                float wf1 = fc * b1, wf2 = fc * b2, wf3 = fc * b3;
#pragma unroll
                for (int r = 0; r < RR; r++) {
                    float rb = gk[r];
                    wf1 = fmaf(rb, w1[r], wf1);
                    wf2 = fmaf(rb, w2[r], wf2);
                    wf3 = fmaf(rb, w3[r], wf3);
                }
                const float* pp = phi + (long long)src * 384;
                float m1  = pp[f]       * wf1;
                float dvv = pp[128 + f] * wf2;
                float dvs = pp[256 + f] * wf3;
                ds += m1;
                const float* vp = vin + (long long)src * 384;
                dv0 = fmaf(vp[f],       dvv, fmaf(u0, dvs, dv0));
                dv1 = fmaf(vp[128 + f], dvv, fmaf(u1, dvs, dv1));
                dv2 = fmaf(vp[256 + f], dvv, fmaf(u2, dvs, dv2));
            }
        }
        long long sa = (long long)a * 128;
        long long va = (long long)a * 384;
        s[sa + f] += ds;
        vout[va + f]       = vin[va + f]       + dv0;
        vout[va + 128 + f] = vin[va + 128 + f] + dv1;
        vout[va + 256 + f] = vin[va + 256 + f] + dv2;
    }
}

// ---------------- per-atom update pieces ------------------------------------
__global__ void cat_kernel(const float* __restrict__ s, const float* __restrict__ vv,
                           float* __restrict__ cat) {
    int i = blockIdx.x * blockDim.x + threadIdx.x;
    if (i >= NA * FF) return;
    int atom = i >> 7, f = i & 127;
    const float* vp = vv + (long long)atom * 384;
    float x0 = vp[f], x1 = vp[128 + f], x2 = vp[256 + f];
    float n = sqrtf(x0 * x0 + x1 * x1 + x2 * x2 + 1e-8f);
    cat[(long long)atom * 256 + f]       = s[i];
    cat[(long long)atom * 256 + 128 + f] = n;
}

__global__ void upd_kernel(const float* __restrict__ uv, const float* __restrict__ vv,
                           const float* __restrict__ a,
                           float* __restrict__ s,
                           const float* __restrict__ vB, float* __restrict__ vA) {
    int i = blockIdx.x * blockDim.x + threadIdx.x;
    if (i >= NA * FF) return;
    int atom = i >> 7, f = i & 127;
    long long off = (long long)atom * 384;
    float u0 = uv[off + f], u1 = uv[off + 128 + f], u2 = uv[off + 256 + f];
    float x0 = vv[off + f], x1 = vv[off + 128 + f], x2 = vv[off + 256 + f];
    float dot = u0 * x0 + u1 * x1 + u2 * x2;
    float a_vv = a[off + f], a_sv = a[off + 128 + f], a_ss = a[off + 256 + f];
    s[i] += a_ss + a_sv * dot;
    vA[off + f]       = vB[off + f]       + a_vv * u0;
    vA[off + 128 + f] = vB[off + 128 + f] + a_vv * u1;
    vA[off + 256 + f] = vB[off + 256 + f] + a_vv * u2;
}

// ---------------- readout: GEMV + molecule segment sum ---------------------
__global__ void out2_kernel(const float* __restrict__ h, const float* __restrict__ w2,
                            const float* __restrict__ b2, const int* __restrict__ mol,
                            float* __restrict__ out) {
    int gw = (blockIdx.x * blockDim.x + threadIdx.x) >> 5;
    int lane = threadIdx.x & 31;
    if (gw >= NA) return;
    const float* hp = h + (long long)gw * FF;
    float sum = 0.f;
#pragma unroll
    for (int i = lane; i < FF; i += 32) sum = fmaf(hp[i], w2[i], sum);
#pragma unroll
    for (int o = 16; o; o >>= 1) sum += __shfl_down_sync(0xffffffffu, sum, o);
    if (lane == 0) atomicAdd(&out[mol[gw]], sum + b2[0]);
}

// ---------------- host-side launch ------------------------------------------
static float* symf(const void* sym) {
    void* p = nullptr;
    cudaGetSymbolAddress(&p, sym);
    return (float*)p;
}
static int* symi(const void* sym) {
    void* p = nullptr;
    cudaGetSymbolAddress(&p, sym);
    return (int*)p;
}

extern "C" void kernel_launch(void* const* d_in, const int* in_sizes, int n_in,
                              void* d_out, int out_size) {
    const int*   z        = (const int*)  d_in[0];
    const float* pos      = (const float*)d_in[1];
    const int*   edge_src = (const int*)  d_in[2];
    const int*   edge_dst = (const int*)  d_in[3];
    const int*   mol_idx  = (const int*)  d_in[4];
    const float* embed    = (const float*)d_in[5];
    const float* msg_w1   = (const float*)d_in[6];
    const float* msg_b1   = (const float*)d_in[7];
    const float* msg_w2   = (const float*)d_in[8];
    const float* msg_b2   = (const float*)d_in[9];
    const float* rbf_w    = (const float*)d_in[10];
    const float* rbf_b    = (const float*)d_in[11];
    const float* upd_u    = (const float*)d_in[12];
    const float* upd_v    = (const float*)d_in[13];
    const float* upd_a1   = (const float*)d_in[14];
    const float* upd_a1b  = (const float*)d_in[15];
    const float* upd_a2   = (const float*)d_in[16];
    const float* upd_a2b  = (const float*)d_in[17];
    const float* out_w1   = (const float*)d_in[18];
    const float* out_b1   = (const float*)d_in[19];
    const float* out_w2   = (const float*)d_in[20];
    const float* out_b2   = (const float*)d_in[21];
    float* out = (float*)d_out;

    float* s   = symf(g_s);
    float* vA  = symf(g_vA);
    float* vB  = symf(g_vB);
    float* h   = symf(g_h);
    float* phi = symf(g_phi);
    float* uv  = symf(g_uv);
    float* vv  = symf(g_vv);
    float* cat = symf(g_cat);
    float* ah  = symf(g_ah);
    float* a   = symf(g_a);
    float* egeo = symf(g_egeo);
    int* esrc   = symi(g_esrc);
    int* rowst  = symi(g_rowstart);
    int* cursor = symi(g_cursor);
    int* count  = symi(g_count);

    // init
    zero_f_kernel<<<1024, 256>>>(vA, NA * 3 * FF);
    zero_i_kernel<<<32, 256>>>(count, NA);
    zero_f_kernel<<<1, 128>>>(out, NMOL);
    embed_kernel<<<(NA * FF + 255) / 256, 256>>>(z, embed, s);

    // CSR + edge geometry
    count_kernel<<<(NE + 255) / 256, 256>>>(edge_dst, count);
    scan_kernel<<<1, 1024>>>(count, rowst, cursor);
    fill_kernel<<<(NE + 255) / 256, 256>>>(edge_src, edge_dst, pos, cursor, egeo, esrc);

    for (int l = 0; l < LL; l++) {
        const float* w1  = msg_w1  + (long long)l * FF * FF;
        const float* bb1 = msg_b1  + (long long)l * FF;
        const float* w2  = msg_w2  + (long long)l * FF * 3 * FF;
        const float* bb2 = msg_b2  + (long long)l * 3 * FF;
        const float* rw  = rbf_w   + (long long)l * RR * 3 * FF;
        const float* rb  = rbf_b   + (long long)l * 3 * FF;
        const float* uu  = upd_u   + (long long)l * FF * FF;
        const float* uvw = upd_v   + (long long)l * FF * FF;
        const float* a1  = upd_a1  + (long long)l * 2 * FF * FF;
        const float* a1b = upd_a1b + (long long)l * FF;
        const float* a2  = upd_a2  + (long long)l * FF * 3 * FF;
        const float* a2b = upd_a2b + (long long)l * 3 * FF;

        gemm_kernel<true ><<<dim3(2, 64),  256>>>(s,   w1, bb1, h,   NA, 128, 128);
        gemm_kernel<false><<<dim3(6, 64),  256>>>(h,   w2, bb2, phi, NA, 384, 128);
        msg_kernel<<<NA / APB, 128>>>(phi, vA, s, vB, rw, rb, egeo, esrc, rowst);
        gemm_kernel<false><<<dim3(2, 192), 256>>>(vB, uu,  nullptr, uv, NA * 3, 128, 128);
        gemm_kernel<false><<<dim3(2, 192), 256>>>(vB, uvw, nullptr, vv, NA * 3, 128, 128);
        cat_kernel<<<(NA * FF + 255) / 256, 256>>>(s, vv, cat);
        gemm_kernel<true ><<<dim3(2, 64),  256>>>(cat, a1, a1b, ah, NA, 128, 256);
        gemm_kernel<false><<<dim3(6, 64),  256>>>(ah,  a2, a2b, a,  NA, 384, 128);
        upd_kernel<<<(NA * FF + 255) / 256, 256>>>(uv, vv, a, s, vB, vA);
    }

    gemm_kernel<true><<<dim3(2, 64), 256>>>(s, out_w1, out_b1, h, NA, 128, 128);
    out2_kernel<<<NA * 32 / 256, 256>>>(h, out_w2, out_b2, mol_idx, out);
}